// round 14
// baseline (speedup 1.0000x reference)
#include <cuda_runtime.h>
#include <math.h>
#include <stdint.h>

#define BB 16
#define NN 2048
#define DD 768
#define NT (NN / 128)               // 16 tiles per dim
#define NPAIR (NT * (NT + 1) / 2)   // 136 upper-tri tile pairs

typedef unsigned long long ull;

// ---- scratch (no dynamic allocation allowed) ----
__device__ float g_fn[(size_t)BB * NN * DD];    // normalized features, 96 MB
__device__ float g_sim[(size_t)BB * NN * NN];   // similarity, 256 MB
__device__ float g_rowsum[BB * NN];
__device__ int   g_order[BB * NN];
__device__ uint16_t g_cand[(size_t)BB * NN * 32];  // top-32 candidate idx per row, 2 MB

__device__ __forceinline__ void argmax_combine(float& v, int& i, float v2, int i2) {
    if (v2 > v || (v2 == v && i2 < i)) { v = v2; i = i2; }
}

__device__ __forceinline__ ull ffma2(ull a, ull b, ull c) {
    ull d;
    asm("fma.rn.f32x2 %0, %1, %2, %3;" : "=l"(d) : "l"(a), "l"(b), "l"(c));
    return d;
}
__device__ __forceinline__ float2 unpack2(ull a) {
    float2 f;
    asm("mov.b64 {%0, %1}, %2;" : "=f"(f.x), "=f"(f.y) : "l"(a));
    return f;
}

__device__ __forceinline__ uint32_t okey(float v) {
    uint32_t u = __float_as_uint(v);
    return (u & 0x80000000u) ? ~u : (u | 0x80000000u);
}
__device__ __forceinline__ float unokey(uint32_t k) {
    uint32_t u = (k & 0x80000000u) ? (k ^ 0x80000000u) : ~k;
    return __uint_as_float(u);
}

// B permuted position for conflict-free fragment reads (R9, measured-good)
__device__ __forceinline__ int bpos(int c) {
    const int g = c >> 6, cl = c & 63;
    const int t3 = cl >> 3, jj = cl & 7;
    return g * 64 + (jj >> 2) * 32 + t3 * 4 + (jj & 3);
}

// A-dup word offset within a k-row for m-index (staggered, conflict-free reads)
// max offset = 3*80 + 3*16 + 8 + 7*2 = 310 (+2 for float2) -> needs ADF >= 312
__device__ __forceinline__ int apos(int m) {
    return (m >> 5) * 80 + ((m >> 3) & 3) * 16 + ((m >> 4) & 1) * 8 + (m & 7) * 2;
}

extern __shared__ char dynsm[];

// ---------------- K1: normalize feature rows ----------------
__global__ void knorm(const float* __restrict__ f) {
    const int row = blockIdx.x;
    const float* src = f + (size_t)row * DD;
    float s = 0.f;
    for (int i = threadIdx.x; i < DD; i += 256) { float v = src[i]; s += v * v; }
    for (int o = 16; o; o >>= 1) s += __shfl_down_sync(0xffffffffu, s, o);
    __shared__ float red[8];
    const int w = threadIdx.x >> 5, l = threadIdx.x & 31;
    if (l == 0) red[w] = s;
    __syncthreads();
    if (w == 0) {
        s = (l < 8) ? red[l] : 0.f;
        for (int o = 4; o; o >>= 1) s += __shfl_down_sync(0xffffffffu, s, o);
        if (l == 0) red[0] = 1.0f / fmaxf(sqrtf(s), 1e-12f);
    }
    __syncthreads();
    const float scale = red[0];
    float* dst = g_fn + (size_t)row * DD;
    for (int i = threadIdx.x; i < DD; i += 256) dst[i] = src[i] * scale;
}

// ---------------- K2: symmetric SGEMM, A pre-duplicated, j-paired acc ----------------
#define ADF 320                                   // A-dup row stride (words)
#define BSF 132                                   // B row stride (words)
#define STG_F (16 * ADF + 16 * BSF)               // 7232 floats per stage
#define GEMM_SMEM (2 * STG_F * 4)                 // 57856 bytes

__global__ void __launch_bounds__(256, 2) kgemm(const float* __restrict__ coords) {
    float* smf = (float*)dynsm;
    __shared__ float2 rc[128];
    __shared__ float2 cc[128];

    int p = blockIdx.x;
    int tmi = 0;
    while (p >= NT - tmi) { p -= NT - tmi; tmi++; }
    const int tni = tmi + p;

    const int b  = blockIdx.z;
    const int tm = tmi * 128;
    const int tn = tni * 128;
    const float*  F = g_fn + (size_t)b * NN * DD;
    const float2* C = (const float2*)(coords + (size_t)b * NN * 2);
    const int tid = threadIdx.x;

    if (tid < 128) rc[tid] = C[tm + tid];
    else           cc[tid - 128] = C[tn + tid - 128];

    // loader indices
    const int lr  = tid >> 2;             // 0..63 (+64)
    const int s4  = (tid & 3) * 4;        // k-seg base 0,4,8,12
    const int ap0 = apos(lr);
    const int ap1 = apos(lr + 64);
    const int bp0 = bpos(lr);
    const int bp1 = bpos(lr + 64);

    // compute indices
    const int wid = tid >> 5, lane = tid & 31;
    const int wm = wid >> 1, wn = wid & 1;
    const int ty3 = lane >> 3, tx3 = lane & 7;
    const int mr = wm * 32 + ty3 * 8;     // row base (8 rows)
    const int nc = wn * 64 + tx3 * 8;     // col base (8 cols)
    const int abase = wm * 80 + ty3 * 16 + (ty3 >> 1) * 8;   // A-dup read base
    const int boff = wn * 64 + tx3 * 4;   // B read offset

    // load chunk 0, store to stage 0
    float4 pa[2], pb[2];
#pragma unroll
    for (int r = 0; r < 2; r++) {
        const int row = lr + r * 64;
        pa[r] = *(const float4*)(F + (size_t)(tm + row) * DD + s4);
        pb[r] = *(const float4*)(F + (size_t)(tn + row) * DD + s4);
    }
    {
        float* Ad_ = smf;
        float* Bs_ = smf + 16 * ADF;
#pragma unroll
        for (int r = 0; r < 2; r++) {
            const int ap = r ? ap1 : ap0;
            const int bp = r ? bp1 : bp0;
            *(float2*)&Ad_[(s4 + 0) * ADF + ap] = make_float2(pa[r].x, pa[r].x);
            *(float2*)&Ad_[(s4 + 1) * ADF + ap] = make_float2(pa[r].y, pa[r].y);
            *(float2*)&Ad_[(s4 + 2) * ADF + ap] = make_float2(pa[r].z, pa[r].z);
            *(float2*)&Ad_[(s4 + 3) * ADF + ap] = make_float2(pa[r].w, pa[r].w);
            Bs_[(s4 + 0) * BSF + bp] = pb[r].x;  Bs_[(s4 + 1) * BSF + bp] = pb[r].y;
            Bs_[(s4 + 2) * BSF + bp] = pb[r].z;  Bs_[(s4 + 3) * BSF + bp] = pb[r].w;
        }
    }
    __syncthreads();

    ull acc2[8][4];
#pragma unroll
    for (int i = 0; i < 8; i++)
#pragma unroll
        for (int j = 0; j < 4; j++) acc2[i][j] = 0ull;

    const int NCH = DD / 16;
#pragma unroll 1
    for (int c = 0; c < NCH; c++) {
        const int s = c & 1;
        const float* Ad_ = smf + s * STG_F;
        const float* Bs_ = Ad_ + 16 * ADF;

        if (c + 1 < NCH) {
            const int k0n = (c + 1) * 16;
#pragma unroll
            for (int r = 0; r < 2; r++) {
                const int row = lr + r * 64;
                pa[r] = *(const float4*)(F + (size_t)(tm + row) * DD + k0n + s4);
                pb[r] = *(const float4*)(F + (size_t)(tn + row) * DD + k0n + s4);
            }
        }

#pragma unroll
        for (int k = 0; k < 16; k++) {
            const float* Ak = &Ad_[k * ADF + abase];
            const ulonglong2 aA = *(const ulonglong2*)(Ak);
            const ulonglong2 aB = *(const ulonglong2*)(Ak + 4);
            const ulonglong2 aC = *(const ulonglong2*)(Ak + 8);
            const ulonglong2 aD = *(const ulonglong2*)(Ak + 12);
            const ulonglong2 b01 = *(const ulonglong2*)&Bs_[k * BSF + boff];
            const ulonglong2 b23 = *(const ulonglong2*)&Bs_[k * BSF + boff + 32];
            ull ad[8] = { aA.x, aA.y, aB.x, aB.y, aC.x, aC.y, aD.x, aD.y };
            ull bp_[4] = { b01.x, b01.y, b23.x, b23.y };
#pragma unroll
            for (int i = 0; i < 8; i++)
#pragma unroll
                for (int jp = 0; jp < 4; jp++)
                    acc2[i][jp] = ffma2(ad[i], bp_[jp], acc2[i][jp]);
        }

        if (c + 1 < NCH) {
            float* Ad2_ = smf + (s ^ 1) * STG_F;
            float* Bs2_ = Ad2_ + 16 * ADF;
#pragma unroll
            for (int r = 0; r < 2; r++) {
                const int ap = r ? ap1 : ap0;
                const int bp = r ? bp1 : bp0;
                *(float2*)&Ad2_[(s4 + 0) * ADF + ap] = make_float2(pa[r].x, pa[r].x);
                *(float2*)&Ad2_[(s4 + 1) * ADF + ap] = make_float2(pa[r].y, pa[r].y);
                *(float2*)&Ad2_[(s4 + 2) * ADF + ap] = make_float2(pa[r].z, pa[r].z);
                *(float2*)&Ad2_[(s4 + 3) * ADF + ap] = make_float2(pa[r].w, pa[r].w);
                Bs2_[(s4 + 0) * BSF + bp] = pb[r].x;  Bs2_[(s4 + 1) * BSF + bp] = pb[r].y;
                Bs2_[(s4 + 2) * BSF + bp] = pb[r].z;  Bs2_[(s4 + 3) * BSF + bp] = pb[r].w;
            }
        }
        __syncthreads();
    }

    float acc[8][8];
#pragma unroll
    for (int i = 0; i < 8; i++)
#pragma unroll
        for (int jp = 0; jp < 4; jp++) {
            const float2 v = unpack2(acc2[i][jp]);
            acc[i][2 * jp + 0] = v.x;
            acc[i][2 * jp + 1] = v.y;
        }

#pragma unroll
    for (int i = 0; i < 8; i++) {
        const float2 r2 = rc[mr + i];
#pragma unroll
        for (int j = 0; j < 8; j++) {
            const float2 c2 = cc[nc + j];
            const float dx = r2.x - c2.x, dy = r2.y - c2.y;
            const float sp = expf(-(dx * dx + dy * dy) * (1.0f / 10000.0f));
            acc[i][j] += 0.5f * sp;
        }
    }

    float* S = g_sim + (size_t)b * NN * NN;
#pragma unroll
    for (int i = 0; i < 8; i++) {
        const int gi = tm + mr + i;
        float4* op = (float4*)(S + (size_t)gi * NN + tn + nc);
        op[0] = make_float4(acc[i][0], acc[i][1], acc[i][2], acc[i][3]);
        op[1] = make_float4(acc[i][4], acc[i][5], acc[i][6], acc[i][7]);
    }

    if (tmi != tni) {
        float (*tb)[BSF] = (float (*)[BSF])dynsm;   // alias stage memory
#pragma unroll
        for (int c0 = 0; c0 < 128; c0 += 32) {
            __syncthreads();
            if ((nc & ~31) == c0) {
#pragma unroll
                for (int j = 0; j < 8; j++)
#pragma unroll
                    for (int i = 0; i < 8; i++)
                        tb[nc + j - c0][mr + i] = acc[i][j];
            }
            __syncthreads();
            const int cc2 = tid >> 3;
            const int seg = (tid & 7) * 16;
            float4* dst = (float4*)(S + (size_t)(tn + c0 + cc2) * NN + tm + seg);
            const float* sr = &tb[cc2][seg];
            dst[0] = make_float4(sr[0],  sr[1],  sr[2],  sr[3]);
            dst[1] = make_float4(sr[4],  sr[5],  sr[6],  sr[7]);
            dst[2] = make_float4(sr[8],  sr[9],  sr[10], sr[11]);
            dst[3] = make_float4(sr[12], sr[13], sr[14], sr[15]);
        }
    }
}

// ---------------- K3: per-row top-32 candidates + fused rowsum (1 warp/row) ----------------
__global__ void __launch_bounds__(256) ktop() {
    const int row = blockIdx.x * 8 + (threadIdx.x >> 5);
    const int lane = threadIdx.x & 31;
    const float4* R4 = (const float4*)(g_sim + (size_t)row * NN);

    ull top[8];
#pragma unroll
    for (int q = 0; q < 8; q++) top[q] = 0ull;
    float thr = -3.0e38f;
    float rsum = 0.f;

#pragma unroll 4
    for (int i = 0; i < 16; i++) {
        const float4 v = R4[i * 32 + lane];
        const int j0 = i * 128 + lane * 4;
        const float vv[4] = { v.x, v.y, v.z, v.w };
        rsum += v.x; rsum += v.y; rsum += v.z; rsum += v.w;
#pragma unroll
        for (int q = 0; q < 4; q++) {
            if (vv[q] >= thr) {
                const ull key = ((ull)okey(vv[q]) << 32) | (uint32_t)(~(j0 + q));
                if (key > top[7]) {
                    top[7] = key;
#pragma unroll
                    for (int t = 7; t >= 1; t--) {
                        if (top[t] > top[t - 1]) { ull tmp = top[t - 1]; top[t - 1] = top[t]; top[t] = tmp; }
                    }
                    thr = (top[7] == 0ull) ? -3.0e38f : unokey((uint32_t)(top[7] >> 32));
                }
            }
        }
    }

    {
        float s = rsum;
#pragma unroll
        for (int o = 16; o; o >>= 1) s += __shfl_xor_sync(0xffffffffu, s, o);
        if (lane == 0) g_rowsum[row] = s;
    }

    const ull k7o = top[7];
    uint32_t keepj = 0;
    ull w = 0;
#pragma unroll 1
    for (int rnd = 0; rnd < 32; rnd++) {
        const ull best = top[0];
        w = best;
#pragma unroll
        for (int o = 16; o; o >>= 1) {
            const ull ow = __shfl_xor_sync(0xffffffffu, w, o);
            if (ow > w) w = ow;
        }
        const unsigned wm = __ballot_sync(0xffffffffu, best == w);
        const int wl = __ffs(wm) - 1;
        if (lane == wl) {
#pragma unroll
            for (int t = 0; t < 7; t++) top[t] = top[t + 1];
            top[7] = 0ull;
        }
        if (lane == rnd) keepj = ~(uint32_t)w;
    }
    const bool unsafe_row = __any_sync(0xffffffffu, k7o > w);
    g_cand[(size_t)row * 32 + lane] = unsafe_row ? (uint16_t)0xFFFFu : (uint16_t)keepj;
}

// ---------------- K4: greedy, 1 warp/batch, single rare branch ----------------
#define GR_CAND 0
#define GR_ORD  131072
#define GR_VIS  139264
#define GR_SMEM 147456

__global__ void __launch_bounds__(256) kgreedy() {
    const int b = blockIdx.x;
    const int tid = threadIdx.x;
    const int lane = tid & 31;
    uint16_t* scand = (uint16_t*)(dynsm + GR_CAND);
    int*      sord  = (int*)(dynsm + GR_ORD);
    unsigned* vis   = (unsigned*)(dynsm + GR_VIS);

    __shared__ float sval[8];
    __shared__ int   sidx[8];

    {
        const uint4* src = (const uint4*)(g_cand + (size_t)b * NN * 32);
        uint4* dst = (uint4*)scand;
        for (int i = tid; i < NN * 32 / 8; i += 256) dst[i] = src[i];
    }
    for (int i = tid; i < 2048; i += 256) vis[i] = (i < NN / 32) ? 0u : 0xFFFFFFFFu;

    {
        const float* rs = g_rowsum + b * NN;
        float v = -3.4e38f; int bi = 0;
#pragma unroll
        for (int q = 0; q < 8; q++) {
            const int j = q * 256 + tid;
            argmax_combine(v, bi, rs[j], j);
        }
        for (int o = 16; o; o >>= 1) {
            const float ov = __shfl_down_sync(0xffffffffu, v, o);
            const int   oi = __shfl_down_sync(0xffffffffu, bi, o);
            argmax_combine(v, bi, ov, oi);
        }
        if (lane == 0) { sval[tid >> 5] = v; sidx[tid >> 5] = bi; }
    }
    __syncthreads();
    if (tid >= 32) return;

    int cur;
    {
        float v = sval[0]; int bi = sidx[0];
#pragma unroll
        for (int q = 1; q < 8; q++) argmax_combine(v, bi, sval[q], sidx[q]);
        cur = bi;
        if (lane == 0) {
            vis[bi >> 5] |= (1u << (bi & 31));
            sord[0] = bi;
        }
    }
    __syncwarp();

    const float* S = g_sim + (size_t)b * NN * NN;

    for (int step = 1; step < NN; step++) {
        const int ci = (int)scand[cur * 32 + lane];
        unsigned vw = vis[ci >> 5];
        const bool unv = !((vw >> (ci & 31)) & 1u);
        const unsigned key = unv ? (((unsigned)lane << 16) | (unsigned)ci) : 0xFFFFFFFFu;
        unsigned kmin = __reduce_min_sync(0xffffffffu, key);
        if (kmin == 0xFFFFFFFFu) {
            // fallback: full row scan (rare)
            const float4* R4 = (const float4*)(S + (size_t)cur * NN);
            float v = -3.4e38f; int bi = 0;
#pragma unroll 4
            for (int i = 0; i < 16; i++) {
                const float4 x = R4[i * 32 + lane];
                const int jb = i * 128 + lane * 4;
                const unsigned vwf = vis[jb >> 5];
                const float x0 = ((vwf >> (jb & 31)) & 1u)       ? -3.0e38f : x.x;
                const float x1 = ((vwf >> ((jb + 1) & 31)) & 1u) ? -3.0e38f : x.y;
                const float x2 = ((vwf >> ((jb + 2) & 31)) & 1u) ? -3.0e38f : x.z;
                const float x3 = ((vwf >> ((jb + 3) & 31)) & 1u) ? -3.0e38f : x.w;
                argmax_combine(v, bi, x0, jb);
                argmax_combine(v, bi, x1, jb + 1);
                argmax_combine(v, bi, x2, jb + 2);
                argmax_combine(v, bi, x3, jb + 3);
            }
#pragma unroll
            for (int o = 16; o; o >>= 1) {
                const float ov = __shfl_down_sync(0xffffffffu, v, o);
                const int   oi = __shfl_down_sync(0xffffffffu, bi, o);
                argmax_combine(v, bi, ov, oi);
            }
            const int jf = __shfl_sync(0xffffffffu, bi, 0);
            kmin = (unsigned)jf;             // winner lane = 0
            vw = vis[jf >> 5];               // uniform reload so lane 0 has j's word
        }
        const int j = (int)(kmin & 0xFFFFu);
        const unsigned neww = vw | (1u << (j & 31));
        const unsigned waddr = (unsigned)__cvta_generic_to_shared(&vis[j >> 5]);
        asm volatile(
            "{\n\t.reg .pred p;\n\t"
            "setp.eq.u32 p, %0, %1;\n\t"
            "@p st.shared.u32 [%2], %3;\n\t}"
            :: "r"((unsigned)lane), "r"(kmin >> 16), "r"(waddr), "r"(neww) : "memory");
        sord[step] = j;
        cur = j;
    }

    for (int i = lane; i < NN; i += 32) g_order[b * NN + i] = sord[i];
}

// ---------------- K5: gather reordered features ----------------
__global__ void kreorder(const float* __restrict__ f, float* __restrict__ out) {
    const int b = blockIdx.y, i = blockIdx.x;
    const int src = g_order[b * NN + i];
    const float4* s = (const float4*)(f + ((size_t)b * NN + src) * DD);
    float4* d = (float4*)(out + ((size_t)b * NN + i) * DD);
    d[threadIdx.x] = s[threadIdx.x];
}

__global__ void korder(float* __restrict__ out) {
    const int t = blockIdx.x * blockDim.x + threadIdx.x;
    if (t < BB * NN) out[(size_t)BB * NN * DD + t] = (float)g_order[t];
}

extern "C" void kernel_launch(void* const* d_in, const int* in_sizes, int n_in,
                              void* d_out, int out_size) {
    const float* features = (const float*)d_in[0];
    const float* coords   = (const float*)d_in[1];
    float* out = (float*)d_out;

    cudaFuncSetAttribute(kgemm, cudaFuncAttributeMaxDynamicSharedMemorySize, GEMM_SMEM);
    cudaFuncSetAttribute(kgreedy, cudaFuncAttributeMaxDynamicSharedMemorySize, GR_SMEM);

    knorm<<<BB * NN, 256>>>(features);

    dim3 gg(NPAIR, 1, BB);
    kgemm<<<gg, 256, GEMM_SMEM>>>(coords);

    ktop<<<(BB * NN) / 8, 256>>>();

    kgreedy<<<BB, 256, GR_SMEM>>>();

    dim3 rg(NN, BB);
    kreorder<<<rg, 192>>>(features, out);

    if ((long long)out_size >= (long long)BB * NN * DD + BB * NN) {
        korder<<<(BB * NN + 255) / 256, 256>>>(out);
    }
}

// round 15
// speedup vs baseline: 1.1386x; 1.1386x over previous
#include <cuda_runtime.h>
#include <math.h>
#include <stdint.h>

#define BB 16
#define NN 2048
#define DD 768
#define NT (NN / 128)               // 16 tiles per dim
#define NPAIR (NT * (NT + 1) / 2)   // 136 upper-tri tile pairs
#define NTILES (NPAIR * BB)         // 2176 work items
#define GPERS 296                   // persistent CTAs (148 SMs x 2)

typedef unsigned long long ull;

// ---- scratch (no dynamic allocation allowed) ----
__device__ float g_fn[(size_t)BB * NN * DD];    // normalized features, 96 MB
__device__ float g_sim[(size_t)BB * NN * NN];   // similarity, 256 MB
__device__ float g_rowsum[BB * NN];
__device__ int   g_order[BB * NN];
__device__ uint16_t g_cand[(size_t)BB * NN * 32];  // top-32 candidate idx per row, 2 MB
__device__ unsigned g_ctr;                      // persistent-GEMM work ticket

__device__ __forceinline__ void argmax_combine(float& v, int& i, float v2, int i2) {
    if (v2 > v || (v2 == v && i2 < i)) { v = v2; i = i2; }
}

__device__ __forceinline__ ull ffma2(ull a, ull b, ull c) {
    ull d;
    asm("fma.rn.f32x2 %0, %1, %2, %3;" : "=l"(d) : "l"(a), "l"(b), "l"(c));
    return d;
}
__device__ __forceinline__ ull pack2(float x, float y) {
    ull r;
    asm("mov.b64 %0, {%1, %2};" : "=l"(r) : "f"(x), "f"(y));
    return r;
}
__device__ __forceinline__ float2 unpack2(ull a) {
    float2 f;
    asm("mov.b64 {%0, %1}, %2;" : "=f"(f.x), "=f"(f.y) : "l"(a));
    return f;
}

__device__ __forceinline__ uint32_t okey(float v) {
    uint32_t u = __float_as_uint(v);
    return (u & 0x80000000u) ? ~u : (u | 0x80000000u);
}
__device__ __forceinline__ float unokey(uint32_t k) {
    uint32_t u = (k & 0x80000000u) ? (k ^ 0x80000000u) : ~k;
    return __uint_as_float(u);
}

// B permuted position for conflict-free fragment reads (R9, measured-good)
__device__ __forceinline__ int bpos(int c) {
    const int g = c >> 6, cl = c & 63;
    const int t3 = cl >> 3, jj = cl & 7;
    return g * 64 + (jj >> 2) * 32 + t3 * 4 + (jj & 3);
}

// ---------------- K0: reset work counter ----------------
__global__ void kreset() { g_ctr = 0u; }

// ---------------- K1: normalize feature rows ----------------
__global__ void knorm(const float* __restrict__ f) {
    const int row = blockIdx.x;
    const float* src = f + (size_t)row * DD;
    float s = 0.f;
    for (int i = threadIdx.x; i < DD; i += 256) { float v = src[i]; s += v * v; }
    for (int o = 16; o; o >>= 1) s += __shfl_down_sync(0xffffffffu, s, o);
    __shared__ float red[8];
    const int w = threadIdx.x >> 5, l = threadIdx.x & 31;
    if (l == 0) red[w] = s;
    __syncthreads();
    if (w == 0) {
        s = (l < 8) ? red[l] : 0.f;
        for (int o = 4; o; o >>= 1) s += __shfl_down_sync(0xffffffffu, s, o);
        if (l == 0) red[0] = 1.0f / fmaxf(sqrtf(s), 1e-12f);
    }
    __syncthreads();
    const float scale = red[0];
    float* dst = g_fn + (size_t)row * DD;
    for (int i = threadIdx.x; i < DD; i += 256) dst[i] = src[i] * scale;
}

// ---------------- K2: persistent symmetric SGEMM (R9 inner core) ----------------
struct ShMM { float As[16][132]; float Bs[16][132]; };
union ShU {
    ShMM  mm[2];
    float tb[32][132];
};

__global__ void __launch_bounds__(256, 2) kgemm(const float* __restrict__ coords) {
    __shared__ __align__(16) ShU sh;
    __shared__ float2 rc[128];
    __shared__ float2 cc[128];
    __shared__ int s_my;

    const int tid = threadIdx.x;
    const int lr  = tid >> 2;
    const int s4  = (tid & 3) * 4;
    const int bp0 = bpos(lr);
    const int bp1 = bpos(lr + 64);

    const int wid = tid >> 5, lane = tid & 31;
    const int wm = wid >> 1, wn = wid & 1;
    const int ty3 = lane >> 3, tx3 = lane & 7;
    const int mr = wm * 32 + ty3 * 8;
    const int nc = wn * 64 + tx3 * 8;
    const int boff = wn * 64 + tx3 * 4;

    for (;;) {
        if (tid == 0) s_my = (int)atomicAdd(&g_ctr, 1u);
        __syncthreads();
        const int my = s_my;
        if (my >= NTILES) break;

        const int b = my / NPAIR;
        int p = my % NPAIR;
        int tmi = 0;
        while (p >= NT - tmi) { p -= NT - tmi; tmi++; }
        const int tni = tmi + p;
        const int tm = tmi * 128;
        const int tn = tni * 128;
        const float*  F = g_fn + (size_t)b * NN * DD;
        const float2* C = (const float2*)(coords + (size_t)b * NN * 2);

        if (tid < 128) rc[tid] = C[tm + tid];
        else           cc[tid - 128] = C[tn + tid - 128];

        float4 pa[2], pb[2];
#pragma unroll
        for (int r = 0; r < 2; r++) {
            const int row = lr + r * 64;
            pa[r] = *(const float4*)(F + (size_t)(tm + row) * DD + s4);
            pb[r] = *(const float4*)(F + (size_t)(tn + row) * DD + s4);
        }
#pragma unroll
        for (int r = 0; r < 2; r++) {
            const int row = lr + r * 64;
            const int bp = r ? bp1 : bp0;
            sh.mm[0].As[s4 + 0][row] = pa[r].x; sh.mm[0].As[s4 + 1][row] = pa[r].y;
            sh.mm[0].As[s4 + 2][row] = pa[r].z; sh.mm[0].As[s4 + 3][row] = pa[r].w;
            sh.mm[0].Bs[s4 + 0][bp] = pb[r].x;  sh.mm[0].Bs[s4 + 1][bp] = pb[r].y;
            sh.mm[0].Bs[s4 + 2][bp] = pb[r].z;  sh.mm[0].Bs[s4 + 3][bp] = pb[r].w;
        }
        __syncthreads();

        ull acc2[4][8];
#pragma unroll
        for (int i = 0; i < 4; i++)
#pragma unroll
            for (int j = 0; j < 8; j++) acc2[i][j] = 0ull;

        const int NCH = DD / 16;
#pragma unroll 1
        for (int c = 0; c < NCH; c++) {
            const int s = c & 1;

            if (c + 1 < NCH) {
                const int k0n = (c + 1) * 16;
#pragma unroll
                for (int r = 0; r < 2; r++) {
                    const int row = lr + r * 64;
                    pa[r] = *(const float4*)(F + (size_t)(tm + row) * DD + k0n + s4);
                    pb[r] = *(const float4*)(F + (size_t)(tn + row) * DD + k0n + s4);
                }
            }

#pragma unroll
            for (int k = 0; k < 16; k++) {
                const ulonglong2 a01 = *(const ulonglong2*)&sh.mm[s].As[k][mr];
                const ulonglong2 a23 = *(const ulonglong2*)&sh.mm[s].As[k][mr + 4];
                const float4 b0 = *(const float4*)&sh.mm[s].Bs[k][boff];
                const float4 b1 = *(const float4*)&sh.mm[s].Bs[k][boff + 32];
                ull av[4] = { a01.x, a01.y, a23.x, a23.y };
                ull bd[8] = { pack2(b0.x, b0.x), pack2(b0.y, b0.y),
                              pack2(b0.z, b0.z), pack2(b0.w, b0.w),
                              pack2(b1.x, b1.x), pack2(b1.y, b1.y),
                              pack2(b1.z, b1.z), pack2(b1.w, b1.w) };
#pragma unroll
                for (int ip = 0; ip < 4; ip++)
#pragma unroll
                    for (int j = 0; j < 8; j++)
                        acc2[ip][j] = ffma2(av[ip], bd[j], acc2[ip][j]);
            }

            if (c + 1 < NCH) {
                const int so = s ^ 1;
#pragma unroll
                for (int r = 0; r < 2; r++) {
                    const int row = lr + r * 64;
                    const int bp = r ? bp1 : bp0;
                    sh.mm[so].As[s4 + 0][row] = pa[r].x; sh.mm[so].As[s4 + 1][row] = pa[r].y;
                    sh.mm[so].As[s4 + 2][row] = pa[r].z; sh.mm[so].As[s4 + 3][row] = pa[r].w;
                    sh.mm[so].Bs[s4 + 0][bp] = pb[r].x;  sh.mm[so].Bs[s4 + 1][bp] = pb[r].y;
                    sh.mm[so].Bs[s4 + 2][bp] = pb[r].z;  sh.mm[so].Bs[s4 + 3][bp] = pb[r].w;
                }
            }
            __syncthreads();
        }

        float acc[8][8];
#pragma unroll
        for (int ip = 0; ip < 4; ip++)
#pragma unroll
            for (int j = 0; j < 8; j++) {
                const float2 v = unpack2(acc2[ip][j]);
                acc[2 * ip + 0][j] = v.x;
                acc[2 * ip + 1][j] = v.y;
            }

#pragma unroll
        for (int i = 0; i < 8; i++) {
            const float2 r2 = rc[mr + i];
#pragma unroll
            for (int j = 0; j < 8; j++) {
                const float2 c2 = cc[nc + j];
                const float dx = r2.x - c2.x, dy = r2.y - c2.y;
                const float sp = expf(-(dx * dx + dy * dy) * (1.0f / 10000.0f));
                acc[i][j] += 0.5f * sp;
            }
        }

        float* S = g_sim + (size_t)b * NN * NN;
#pragma unroll
        for (int i = 0; i < 8; i++) {
            const int gi = tm + mr + i;
            float4* op = (float4*)(S + (size_t)gi * NN + tn + nc);
            op[0] = make_float4(acc[i][0], acc[i][1], acc[i][2], acc[i][3]);
            op[1] = make_float4(acc[i][4], acc[i][5], acc[i][6], acc[i][7]);
        }

        if (tmi != tni) {
#pragma unroll
            for (int c0 = 0; c0 < 128; c0 += 32) {
                __syncthreads();
                if ((nc & ~31) == c0) {
#pragma unroll
                    for (int j = 0; j < 8; j++)
#pragma unroll
                        for (int i = 0; i < 8; i++)
                            sh.tb[nc + j - c0][mr + i] = acc[i][j];
                }
                __syncthreads();
                const int cc2 = tid >> 3;
                const int seg = (tid & 7) * 16;
                float4* dst = (float4*)(S + (size_t)(tn + c0 + cc2) * NN + tm + seg);
                const float* sr = &sh.tb[cc2][seg];
                dst[0] = make_float4(sr[0],  sr[1],  sr[2],  sr[3]);
                dst[1] = make_float4(sr[4],  sr[5],  sr[6],  sr[7]);
                dst[2] = make_float4(sr[8],  sr[9],  sr[10], sr[11]);
                dst[3] = make_float4(sr[12], sr[13], sr[14], sr[15]);
            }
        }
        __syncthreads();           // protect smem reuse before next ticket
    }
}

// ---------------- K3: per-row top-32 candidates + fused rowsum (1 warp/row) ----------------
__global__ void __launch_bounds__(256) ktop() {
    const int row = blockIdx.x * 8 + (threadIdx.x >> 5);
    const int lane = threadIdx.x & 31;
    const float4* R4 = (const float4*)(g_sim + (size_t)row * NN);

    ull top[8];
#pragma unroll
    for (int q = 0; q < 8; q++) top[q] = 0ull;
    float thr = -3.0e38f;
    float rsum = 0.f;

#pragma unroll 4
    for (int i = 0; i < 16; i++) {
        const float4 v = R4[i * 32 + lane];
        const int j0 = i * 128 + lane * 4;
        const float vv[4] = { v.x, v.y, v.z, v.w };
        rsum += v.x; rsum += v.y; rsum += v.z; rsum += v.w;
#pragma unroll
        for (int q = 0; q < 4; q++) {
            if (vv[q] >= thr) {
                const ull key = ((ull)okey(vv[q]) << 32) | (uint32_t)(~(j0 + q));
                if (key > top[7]) {
                    top[7] = key;
#pragma unroll
                    for (int t = 7; t >= 1; t--) {
                        if (top[t] > top[t - 1]) { ull tmp = top[t - 1]; top[t - 1] = top[t]; top[t] = tmp; }
                    }
                    thr = (top[7] == 0ull) ? -3.0e38f : unokey((uint32_t)(top[7] >> 32));
                }
            }
        }
    }

    {
        float s = rsum;
#pragma unroll
        for (int o = 16; o; o >>= 1) s += __shfl_xor_sync(0xffffffffu, s, o);
        if (lane == 0) g_rowsum[row] = s;
    }

    const ull k7o = top[7];
    uint32_t keepj = 0;
    ull w = 0;
#pragma unroll 1
    for (int rnd = 0; rnd < 32; rnd++) {
        const ull best = top[0];
        w = best;
#pragma unroll
        for (int o = 16; o; o >>= 1) {
            const ull ow = __shfl_xor_sync(0xffffffffu, w, o);
            if (ow > w) w = ow;
        }
        const unsigned wm = __ballot_sync(0xffffffffu, best == w);
        const int wl = __ffs(wm) - 1;
        if (lane == wl) {
#pragma unroll
            for (int t = 0; t < 7; t++) top[t] = top[t + 1];
            top[7] = 0ull;
        }
        if (lane == rnd) keepj = ~(uint32_t)w;
    }
    const bool unsafe_row = __any_sync(0xffffffffu, k7o > w);
    g_cand[(size_t)row * 32 + lane] = unsafe_row ? (uint16_t)0xFFFFu : (uint16_t)keepj;
}

// ---------------- K4: greedy, 1 warp/batch, single rare branch ----------------
#define GR_CAND 0
#define GR_ORD  131072
#define GR_VIS  139264
#define GR_SMEM 147456

extern __shared__ char gsm[];

__global__ void __launch_bounds__(256) kgreedy() {
    const int b = blockIdx.x;
    const int tid = threadIdx.x;
    const int lane = tid & 31;
    uint16_t* scand = (uint16_t*)(gsm + GR_CAND);
    int*      sord  = (int*)(gsm + GR_ORD);
    unsigned* vis   = (unsigned*)(gsm + GR_VIS);

    __shared__ float sval[8];
    __shared__ int   sidx[8];

    {
        const uint4* src = (const uint4*)(g_cand + (size_t)b * NN * 32);
        uint4* dst = (uint4*)scand;
        for (int i = tid; i < NN * 32 / 8; i += 256) dst[i] = src[i];
    }
    for (int i = tid; i < 2048; i += 256) vis[i] = (i < NN / 32) ? 0u : 0xFFFFFFFFu;

    {
        const float* rs = g_rowsum + b * NN;
        float v = -3.4e38f; int bi = 0;
#pragma unroll
        for (int q = 0; q < 8; q++) {
            const int j = q * 256 + tid;
            argmax_combine(v, bi, rs[j], j);
        }
        for (int o = 16; o; o >>= 1) {
            const float ov = __shfl_down_sync(0xffffffffu, v, o);
            const int   oi = __shfl_down_sync(0xffffffffu, bi, o);
            argmax_combine(v, bi, ov, oi);
        }
        if (lane == 0) { sval[tid >> 5] = v; sidx[tid >> 5] = bi; }
    }
    __syncthreads();
    if (tid >= 32) return;

    int cur;
    {
        float v = sval[0]; int bi = sidx[0];
#pragma unroll
        for (int q = 1; q < 8; q++) argmax_combine(v, bi, sval[q], sidx[q]);
        cur = bi;
        if (lane == 0) {
            vis[bi >> 5] |= (1u << (bi & 31));
            sord[0] = bi;
        }
    }
    __syncwarp();

    const float* S = g_sim + (size_t)b * NN * NN;

    for (int step = 1; step < NN; step++) {
        const int ci = (int)scand[cur * 32 + lane];
        unsigned vw = vis[ci >> 5];
        const bool unv = !((vw >> (ci & 31)) & 1u);
        const unsigned key = unv ? (((unsigned)lane << 16) | (unsigned)ci) : 0xFFFFFFFFu;
        unsigned kmin = __reduce_min_sync(0xffffffffu, key);
        if (__builtin_expect(kmin == 0xFFFFFFFFu, 0)) {
            // fallback: full row scan (rare)
            const float4* R4 = (const float4*)(S + (size_t)cur * NN);
            float v = -3.4e38f; int bi = 0;
#pragma unroll 4
            for (int i = 0; i < 16; i++) {
                const float4 x = R4[i * 32 + lane];
                const int jb = i * 128 + lane * 4;
                const unsigned vwf = vis[jb >> 5];
                const float x0 = ((vwf >> (jb & 31)) & 1u)       ? -3.0e38f : x.x;
                const float x1 = ((vwf >> ((jb + 1) & 31)) & 1u) ? -3.0e38f : x.y;
                const float x2 = ((vwf >> ((jb + 2) & 31)) & 1u) ? -3.0e38f : x.z;
                const float x3 = ((vwf >> ((jb + 3) & 31)) & 1u) ? -3.0e38f : x.w;
                argmax_combine(v, bi, x0, jb);
                argmax_combine(v, bi, x1, jb + 1);
                argmax_combine(v, bi, x2, jb + 2);
                argmax_combine(v, bi, x3, jb + 3);
            }
#pragma unroll
            for (int o = 16; o; o >>= 1) {
                const float ov = __shfl_down_sync(0xffffffffu, v, o);
                const int   oi = __shfl_down_sync(0xffffffffu, bi, o);
                argmax_combine(v, bi, ov, oi);
            }
            const int jf = __shfl_sync(0xffffffffu, bi, 0);
            kmin = (unsigned)jf;             // winner lane = 0
            vw = vis[jf >> 5];               // uniform reload so lane 0 has j's word
        }
        const int j = (int)(kmin & 0xFFFFu);
        const unsigned neww = vw | (1u << (j & 31));
        const unsigned waddr = (unsigned)__cvta_generic_to_shared(&vis[j >> 5]);
        asm volatile(
            "{\n\t.reg .pred p;\n\t"
            "setp.eq.u32 p, %0, %1;\n\t"
            "@p st.shared.u32 [%2], %3;\n\t}"
            :: "r"((unsigned)lane), "r"(kmin >> 16), "r"(waddr), "r"(neww) : "memory");
        sord[step] = j;
        cur = j;
    }

    for (int i = lane; i < NN; i += 32) g_order[b * NN + i] = sord[i];
}

// ---------------- K5: gather reordered features ----------------
__global__ void kreorder(const float* __restrict__ f, float* __restrict__ out) {
    const int b = blockIdx.y, i = blockIdx.x;
    const int src = g_order[b * NN + i];
    const float4* s = (const float4*)(f + ((size_t)b * NN + src) * DD);
    float4* d = (float4*)(out + ((size_t)b * NN + i) * DD);
    d[threadIdx.x] = s[threadIdx.x];
}

__global__ void korder(float* __restrict__ out) {
    const int t = blockIdx.x * blockDim.x + threadIdx.x;
    if (t < BB * NN) out[(size_t)BB * NN * DD + t] = (float)g_order[t];
}

extern "C" void kernel_launch(void* const* d_in, const int* in_sizes, int n_in,
                              void* d_out, int out_size) {
    const float* features = (const float*)d_in[0];
    const float* coords   = (const float*)d_in[1];
    float* out = (float*)d_out;

    cudaFuncSetAttribute(kgreedy, cudaFuncAttributeMaxDynamicSharedMemorySize, GR_SMEM);

    kreset<<<1, 1>>>();

    knorm<<<BB * NN, 256>>>(features);

    kgemm<<<GPERS, 256>>>(coords);

    ktop<<<(BB * NN) / 8, 256>>>();

    kgreedy<<<BB, 256, GR_SMEM>>>();

    dim3 rg(NN, BB);
    kreorder<<<rg, 192>>>(features, out);

    if ((long long)out_size >= (long long)BB * NN * DD + BB * NN) {
        korder<<<(BB * NN + 255) / 256, 256>>>(out);
    }
}